// round 2
// baseline (speedup 1.0000x reference)
// Fused gating-score kernel — base sm_100 target (no tcgen05/TMA available).
// Stage 1: mma.sync tf32 pipelined GEMM  P[8192,5120] = hs @ [q_w;k_w]^T (+bias)
// Stage 2: warp-per-(s,h) RMSNorm + logit + logistic score epilogue.
#include <cuda_runtime.h>
#include <cstdint>

namespace cfg {
constexpr int S  = 8192;
constexpr int D  = 4096;
constexpr int H  = 8;
constexpr int G  = 4;
constexpr int HD = 128;
constexpr int NQ = H * G * HD;   // 4096
constexpr int NK = H * HD;       // 1024
constexpr int NT = NQ + NK;      // 5120

constexpr int BM = 128;
constexpr int BN = 128;
constexpr int BK = 32;
constexpr int KITERS = D / BK;       // 128
constexpr int STAGES = 3;
constexpr int TM_TILES = S / BM;     // 64
constexpr int TN_TILES = NT / BN;    // 40
constexpr int GROUP_TM = 16;

constexpr int LDS_STRIDE = BK + 4;   // 36 floats: conflict-free frag loads
constexpr int TILE_FLOATS = BM * LDS_STRIDE;          // 4608
constexpr int STAGE_FLOATS = 2 * TILE_FLOATS;         // A then B
constexpr int SMEM_BYTES = STAGES * STAGE_FLOATS * 4; // 110592
}  // namespace cfg

__device__ float g_proj[(size_t)cfg::S * cfg::NT];   // 168 MB static scratch

// ---------------------------------------------------------------- helpers
__device__ __forceinline__ uint32_t smem_to_u32(const void* p) {
    uint32_t a;
    asm("{ .reg .u64 t; cvta.to.shared.u64 t, %1; cvt.u32.u64 %0, t; }"
        : "=r"(a) : "l"(p));
    return a;
}

__device__ __forceinline__ void cp_async16(uint32_t dst, const void* src) {
    asm volatile("cp.async.cg.shared.global [%0], [%1], 16;"
                 :: "r"(dst), "l"(src) : "memory");
}
__device__ __forceinline__ void cp_commit() {
    asm volatile("cp.async.commit_group;" ::: "memory");
}
template <int N>
__device__ __forceinline__ void cp_wait() {
    asm volatile("cp.async.wait_group %0;" :: "n"(N) : "memory");
}

__device__ __forceinline__ uint32_t f2tf32(float f) {
    uint32_t r;
    asm("cvt.rna.tf32.f32 %0, %1;" : "=r"(r) : "f"(f));
    return r;
}

__device__ __forceinline__ void mma_tf32(float c[4], const uint32_t a[4],
                                         const uint32_t b[2]) {
    asm volatile(
        "mma.sync.aligned.m16n8k8.row.col.f32.tf32.tf32.f32 "
        "{%0,%1,%2,%3}, {%4,%5,%6,%7}, {%8,%9}, {%0,%1,%2,%3};"
        : "+f"(c[0]), "+f"(c[1]), "+f"(c[2]), "+f"(c[3])
        : "r"(a[0]), "r"(a[1]), "r"(a[2]), "r"(a[3]), "r"(b[0]), "r"(b[1]));
}

// ---------------------------------------------------------------- GEMM
__global__ void __launch_bounds__(256, 2) proj_gemm_kernel(
    const float* __restrict__ hs,
    const float* __restrict__ qw,
    const float* __restrict__ kw,
    const float* __restrict__ q_b)
{
    using namespace cfg;
    extern __shared__ float smem[];
    const uint32_t smem_u32 = smem_to_u32(smem);

    const int tid    = threadIdx.x;
    const int wid    = tid >> 5;
    const int lane   = tid & 31;
    const int warp_m = wid >> 2;          // 0..1  (64 rows each)
    const int warp_n = wid & 3;           // 0..3  (32 cols each)
    const int g      = lane >> 2;         // 0..7
    const int tg     = lane & 3;          // 0..3

    // L2-friendly rasterization: tm fastest within groups of GROUP_TM
    const int bid   = blockIdx.x;
    const int group = bid / (GROUP_TM * TN_TILES);
    const int lm    = bid % (GROUP_TM * TN_TILES);
    const int tm    = group * GROUP_TM + (lm % GROUP_TM);
    const int tn    = lm / GROUP_TM;

    // B source rows: q_w for tiles [0,32), k_w for [32,40)
    const float* bsrc = (tn * BN < NQ) ? (qw + (size_t)(tn * BN) * D)
                                       : (kw + (size_t)(tn * BN - NQ) * D);
    const float* asrc = hs + (size_t)(tm * BM) * D;

    // cp.async mapping: 256 threads x 4 chunks of 16B per tile
    const int c_row = tid >> 3;        // 0..31 (then +32,+64,+96)
    const int c_c4  = tid & 7;         // 16B chunk within 128B row
    const float* a_g = asrc + (size_t)c_row * D + c_c4 * 4;
    const float* b_g = bsrc + (size_t)c_row * D + c_c4 * 4;
    const uint32_t a_s_base = smem_u32 + (c_row * LDS_STRIDE + c_c4 * 4) * 4;
    const uint32_t b_s_base = a_s_base + TILE_FLOATS * 4;
    const size_t row_step = (size_t)32 * D;            // +32 rows
    const uint32_t s_row_step = 32 * LDS_STRIDE * 4;

    auto issue_stage = [&](int kt, int st) {
        const uint32_t so = (uint32_t)st * STAGE_FLOATS * 4;
        const int ko = kt * BK;
        #pragma unroll
        for (int i = 0; i < 4; ++i) {
            cp_async16(a_s_base + so + i * s_row_step, a_g + i * row_step + ko);
            cp_async16(b_s_base + so + i * s_row_step, b_g + i * row_step + ko);
        }
        cp_commit();
    };

    // prologue
    #pragma unroll
    for (int s = 0; s < STAGES - 1; ++s) issue_stage(s, s);

    float acc[4][4][4];
    #pragma unroll
    for (int mt = 0; mt < 4; ++mt)
        #pragma unroll
        for (int nt = 0; nt < 4; ++nt)
            #pragma unroll
            for (int j = 0; j < 4; ++j) acc[mt][nt][j] = 0.0f;

    const int a_row0 = warp_m * 64 + g;       // +mt*16, +8
    const int b_row0 = warp_n * 32 + g;       // +nt*8

    int st = 0;
    for (int kt = 0; kt < KITERS; ++kt) {
        if (kt < KITERS - 1) cp_wait<STAGES - 2>(); else cp_wait<0>();
        __syncthreads();

        if (kt + STAGES - 1 < KITERS)
            issue_stage(kt + STAGES - 1, (st + STAGES - 1) % STAGES);

        const float* As = smem + st * STAGE_FLOATS;
        const float* Bs = As + TILE_FLOATS;

        #pragma unroll
        for (int ks = 0; ks < BK / 8; ++ks) {
            const int kc = ks * 8 + tg;
            uint32_t afr[4][4];
            #pragma unroll
            for (int mt = 0; mt < 4; ++mt) {
                const float* p = As + (a_row0 + mt * 16) * LDS_STRIDE + kc;
                afr[mt][0] = f2tf32(p[0]);
                afr[mt][1] = f2tf32(p[8 * LDS_STRIDE]);
                afr[mt][2] = f2tf32(p[4]);
                afr[mt][3] = f2tf32(p[8 * LDS_STRIDE + 4]);
            }
            uint32_t bfr[4][2];
            #pragma unroll
            for (int nt = 0; nt < 4; ++nt) {
                const float* p = Bs + (b_row0 + nt * 8) * LDS_STRIDE + kc;
                bfr[nt][0] = f2tf32(p[0]);
                bfr[nt][1] = f2tf32(p[4]);
            }
            #pragma unroll
            for (int mt = 0; mt < 4; ++mt)
                #pragma unroll
                for (int nt = 0; nt < 4; ++nt)
                    mma_tf32(acc[mt][nt], afr[mt], bfr[nt]);
        }
        if (++st == STAGES) st = 0;
        __syncthreads();
    }

    // epilogue: bias + store to scratch
    const int n_base = tn * BN + warp_n * 32;
    float2 bias[4];
    #pragma unroll
    for (int nt = 0; nt < 4; ++nt) {
        const int n0 = n_base + nt * 8 + tg * 2;
        bias[nt].x = (n0 < NQ) ? q_b[n0] : 0.0f;
        bias[nt].y = (n0 + 1 < NQ) ? q_b[n0 + 1] : 0.0f;
    }
    #pragma unroll
    for (int mt = 0; mt < 4; ++mt) {
        const int r0 = tm * BM + warp_m * 64 + mt * 16 + g;
        float* p0 = g_proj + (size_t)r0 * NT + n_base;
        float* p1 = p0 + (size_t)8 * NT;
        #pragma unroll
        for (int nt = 0; nt < 4; ++nt) {
            const int no = nt * 8 + tg * 2;
            *reinterpret_cast<float2*>(p0 + no) =
                make_float2(acc[mt][nt][0] + bias[nt].x, acc[mt][nt][1] + bias[nt].y);
            *reinterpret_cast<float2*>(p1 + no) =
                make_float2(acc[mt][nt][2] + bias[nt].x, acc[mt][nt][3] + bias[nt].y);
        }
    }
}

// ---------------------------------------------------------------- score
__global__ void __launch_bounds__(256) score_kernel(
    const float* __restrict__ q_norm_w,
    const float* __restrict__ k_norm_w,
    const float* __restrict__ k_base,
    const float* __restrict__ b,
    float* __restrict__ out)
{
    using namespace cfg;
    const int warp = blockIdx.x * (blockDim.x >> 5) + (threadIdx.x >> 5);
    const int lane = threadIdx.x & 31;
    const int h = warp & (H - 1);
    const int s = warp >> 3;
    const float* base = g_proj + (size_t)s * NT;

    const float4 wq = *reinterpret_cast<const float4*>(q_norm_w + lane * 4);
    const float4 wk = *reinterpret_cast<const float4*>(k_norm_w + lane * 4);
    const float4 kb = *reinterpret_cast<const float4*>(k_base + h * HD + lane * 4);
    const float4 kv = *reinterpret_cast<const float4*>(base + NQ + h * HD + lane * 4);

    float ssk = kv.x * kv.x + kv.y * kv.y + kv.z * kv.z + kv.w * kv.w;
    #pragma unroll
    for (int o = 16; o > 0; o >>= 1) ssk += __shfl_xor_sync(0xFFFFFFFFu, ssk, o);
    const float rk = rsqrtf(ssk * (1.0f / HD) + 1e-6f);
    const float kn0 = kv.x * rk * wk.x;
    const float kn1 = kv.y * rk * wk.y;
    const float kn2 = kv.z * rk * wk.z;
    const float kn3 = kv.w * rk * wk.w;

    const float inv_scale = 0.08838834764831845f;  // 1/sqrt(128)
    float score = 0.0f;
    #pragma unroll
    for (int gi = 0; gi < G; ++gi) {
        const float4 qv = *reinterpret_cast<const float4*>(
            base + h * (G * HD) + gi * HD + lane * 4);
        float s1 = qv.x * qv.x + qv.y * qv.y + qv.z * qv.z + qv.w * qv.w;
        const float qw0 = qv.x * wq.x, qw1 = qv.y * wq.y;
        const float qw2 = qv.z * wq.z, qw3 = qv.w * wq.w;
        float s2 = kn0 * qw0 + kn1 * qw1 + kn2 * qw2 + kn3 * qw3;
        float s3 = kb.x * qw0 + kb.y * qw1 + kb.z * qw2 + kb.w * qw3;
        #pragma unroll
        for (int o = 16; o > 0; o >>= 1) {
            s1 += __shfl_xor_sync(0xFFFFFFFFu, s1, o);
            s2 += __shfl_xor_sync(0xFFFFFFFFu, s2, o);
            s3 += __shfl_xor_sync(0xFFFFFFFFu, s3, o);
        }
        const float rq = rsqrtf(s1 * (1.0f / HD) + 1e-6f);
        const float diff = (s3 - s2) * rq * inv_scale - b[h * G + gi];
        score += 1.0f / (1.0f + expf(diff));
    }
    if (lane == 0) out[h * S + s] = score * 0.25f;
}

// ---------------------------------------------------------------- host
extern "C" void kernel_launch(void* const* d_in, const int* in_sizes, int n_in,
                              void* d_out, int out_size) {
    using namespace cfg;
    const float* hs    = (const float*)d_in[0];
    const float* qw    = (const float*)d_in[1];
    const float* qb    = (const float*)d_in[2];
    const float* kw    = (const float*)d_in[3];
    const float* qnw   = (const float*)d_in[4];
    const float* knw   = (const float*)d_in[5];
    const float* kbase = (const float*)d_in[6];
    const float* bvec  = (const float*)d_in[7];
    float* out         = (float*)d_out;

    static bool attr_set = false;
    if (!attr_set) {
        cudaFuncSetAttribute(proj_gemm_kernel,
                             cudaFuncAttributeMaxDynamicSharedMemorySize, SMEM_BYTES);
        attr_set = true;
    }

    proj_gemm_kernel<<<TM_TILES * TN_TILES, 256, SMEM_BYTES>>>(hs, qw, kw, qb);
    score_kernel<<<(S * H) / 8, 256>>>(qnw, knw, kbase, bvec, out);
}

// round 3
// speedup vs baseline: 2.7371x; 2.7371x over previous
// Fused gating-score kernel — base sm_100 target (legacy mma.sync path).
// Stage 0: fp32 -> fp16 conversion of hs and [q_w;k_w] into static buffers.
// Stage 1: mma.sync fp16 (f32 accum) pipelined GEMM with ldmatrix + XOR swizzle.
// Stage 2: warp-per-(s,h) RMSNorm + logit + logistic score epilogue.
#include <cuda_runtime.h>
#include <cuda_fp16.h>
#include <cstdint>

namespace cfg {
constexpr int S  = 8192;
constexpr int D  = 4096;
constexpr int H  = 8;
constexpr int G  = 4;
constexpr int HD = 128;
constexpr int NQ = H * G * HD;   // 4096
constexpr int NK = H * HD;       // 1024
constexpr int NT = NQ + NK;      // 5120

constexpr int BM = 128;
constexpr int BN = 128;
constexpr int BK = 64;               // halves per k-step (128 B rows)
constexpr int KITERS = D / BK;       // 64
constexpr int STAGES = 3;
constexpr int TM_TILES = S / BM;     // 64
constexpr int TN_TILES = NT / BN;    // 40
constexpr int GROUP_TM = 16;

constexpr int TILE_BYTES  = BM * BK * 2;            // 16 KB
constexpr int STAGE_BYTES = 2 * TILE_BYTES;         // 32 KB (A then B)
constexpr int SMEM_BYTES  = STAGES * STAGE_BYTES;   // 96 KB
}  // namespace cfg

__device__ float  g_proj[(size_t)cfg::S * cfg::NT];       // 168 MB scratch
__device__ __half g_hs_h[(size_t)cfg::S * cfg::D];        // 64 MB
__device__ __half g_w_h[(size_t)cfg::NT * cfg::D];        // 40 MB

// ---------------------------------------------------------------- helpers
__device__ __forceinline__ uint32_t smem_to_u32(const void* p) {
    uint32_t a;
    asm("{ .reg .u64 t; cvta.to.shared.u64 t, %1; cvt.u32.u64 %0, t; }"
        : "=r"(a) : "l"(p));
    return a;
}

__device__ __forceinline__ void cp_async16(uint32_t dst, const void* src) {
    asm volatile("cp.async.cg.shared.global [%0], [%1], 16;"
                 :: "r"(dst), "l"(src) : "memory");
}
__device__ __forceinline__ void cp_commit() {
    asm volatile("cp.async.commit_group;" ::: "memory");
}
template <int N>
__device__ __forceinline__ void cp_wait() {
    asm volatile("cp.async.wait_group %0;" :: "n"(N) : "memory");
}

__device__ __forceinline__ void ldsm_x4(uint32_t r[4], uint32_t addr) {
    asm volatile("ldmatrix.sync.aligned.m8n8.x4.shared.b16 {%0,%1,%2,%3}, [%4];"
                 : "=r"(r[0]), "=r"(r[1]), "=r"(r[2]), "=r"(r[3]) : "r"(addr));
}

__device__ __forceinline__ void mma_f16(float c[4], const uint32_t a[4],
                                        uint32_t b0, uint32_t b1) {
    asm volatile(
        "mma.sync.aligned.m16n8k16.row.col.f32.f16.f16.f32 "
        "{%0,%1,%2,%3}, {%4,%5,%6,%7}, {%8,%9}, {%0,%1,%2,%3};"
        : "+f"(c[0]), "+f"(c[1]), "+f"(c[2]), "+f"(c[3])
        : "r"(a[0]), "r"(a[1]), "r"(a[2]), "r"(a[3]), "r"(b0), "r"(b1));
}

// ---------------------------------------------------------------- convert
__global__ void __launch_bounds__(256) convert_kernel(
    const float* __restrict__ hs,
    const float* __restrict__ qw,
    const float* __restrict__ kw)
{
    using namespace cfg;
    const size_t HS4 = (size_t)S * D / 4;
    const size_t QW4 = (size_t)NQ * D / 4;
    const size_t KW4 = (size_t)NK * D / 4;
    const size_t i = (size_t)blockIdx.x * blockDim.x + threadIdx.x;

    const float* src;
    __half* dst;
    size_t off;
    if (i < HS4)             { src = hs; dst = g_hs_h; off = i; }
    else if (i < HS4 + QW4)  { src = qw; dst = g_w_h;  off = i - HS4; }
    else                     { src = kw; dst = g_w_h + (size_t)NQ * D;
                               off = i - HS4 - QW4; }
    const float4 v = reinterpret_cast<const float4*>(src)[off];
    __half2 h0 = __floats2half2_rn(v.x, v.y);
    __half2 h1 = __floats2half2_rn(v.z, v.w);
    reinterpret_cast<__half2*>(dst)[off * 2]     = h0;
    reinterpret_cast<__half2*>(dst)[off * 2 + 1] = h1;
}

// ---------------------------------------------------------------- GEMM
__global__ void __launch_bounds__(256, 2) proj_gemm_kernel(
    const float* __restrict__ q_b)
{
    using namespace cfg;
    extern __shared__ char smem[];
    const uint32_t smem_u32 = smem_to_u32(smem);

    const int tid    = threadIdx.x;
    const int wid    = tid >> 5;
    const int lane   = tid & 31;
    const int warp_m = wid >> 2;          // 0..1  (64 rows)
    const int warp_n = wid & 3;           // 0..3  (32 cols)
    const int g      = lane >> 2;         // 0..7
    const int tg     = lane & 3;          // 0..3

    // L2-friendly rasterization
    const int bid   = blockIdx.x;
    const int group = bid / (GROUP_TM * TN_TILES);
    const int lm    = bid % (GROUP_TM * TN_TILES);
    const int tm    = group * GROUP_TM + (lm % GROUP_TM);
    const int tn    = lm / GROUP_TM;

    const __half* asrc = g_hs_h + (size_t)(tm * BM) * D;
    const __half* bsrc = g_w_h  + (size_t)(tn * BN) * D;

    // cp.async mapping: row = tid>>3 (+32 steps), chunk c = tid&7 (16B chunks)
    const int c_row = tid >> 3;
    const int c_c   = tid & 7;
    const __half* a_g = asrc + (size_t)c_row * D + c_c * 8;
    const __half* b_g = bsrc + (size_t)c_row * D + c_c * 8;
    const uint32_t a_s_off = (uint32_t)(c_row * 128 + ((c_c ^ (c_row & 7)) << 4));
    const size_t   row_step   = (size_t)32 * D;
    const uint32_t s_row_step = 32 * 128;

    auto issue_stage = [&](int kt, int st) {
        const uint32_t so = smem_u32 + (uint32_t)st * STAGE_BYTES;
        const int ko = kt * BK;
        #pragma unroll
        for (int i = 0; i < 4; ++i) {
            cp_async16(so + a_s_off + i * s_row_step, a_g + i * row_step + ko);
            cp_async16(so + TILE_BYTES + a_s_off + i * s_row_step,
                       b_g + i * row_step + ko);
        }
        cp_commit();
    };

    #pragma unroll
    for (int s = 0; s < STAGES - 1; ++s) issue_stage(s, s);

    float acc[4][4][4];
    #pragma unroll
    for (int mt = 0; mt < 4; ++mt)
        #pragma unroll
        for (int nt = 0; nt < 4; ++nt)
            #pragma unroll
            for (int j = 0; j < 4; ++j) acc[mt][nt][j] = 0.0f;

    // ldmatrix per-lane addressing
    const int a_row = warp_m * 64 + (lane & 15);       // + mt*16
    const int a_dc  = lane >> 4;                       // chunk +0/+1
    const int a_rw  = a_row & 7;
    const int b_row = warp_n * 32 + (lane & 7) + ((lane & 16) >> 1);  // + pr*16
    const int b_dc  = (lane >> 3) & 1;
    const int b_rw  = lane & 7;

    int st = 0;
    for (int kt = 0; kt < KITERS; ++kt) {
        if (kt < KITERS - 1) cp_wait<STAGES - 2>(); else cp_wait<0>();
        __syncthreads();

        if (kt + STAGES - 1 < KITERS)
            issue_stage(kt + STAGES - 1, (st + STAGES - 1) % STAGES);

        const uint32_t As = smem_u32 + st * STAGE_BYTES;
        const uint32_t Bs = As + TILE_BYTES;

        #pragma unroll
        for (int ks = 0; ks < BK / 16; ++ks) {
            const int kc = ks * 2;
            uint32_t afr[4][4];
            #pragma unroll
            for (int mt = 0; mt < 4; ++mt)
                ldsm_x4(afr[mt], As + (a_row + mt * 16) * 128 +
                                  (((kc + a_dc) ^ a_rw) << 4));
            uint32_t bfr[2][4];
            #pragma unroll
            for (int pr = 0; pr < 2; ++pr)
                ldsm_x4(bfr[pr], Bs + (b_row + pr * 16) * 128 +
                                  (((kc + b_dc) ^ b_rw) << 4));
            #pragma unroll
            for (int mt = 0; mt < 4; ++mt) {
                #pragma unroll
                for (int nt = 0; nt < 4; ++nt)
                    mma_f16(acc[mt][nt], afr[mt],
                            bfr[nt >> 1][(nt & 1) * 2],
                            bfr[nt >> 1][(nt & 1) * 2 + 1]);
            }
        }
        if (++st == STAGES) st = 0;
        __syncthreads();
    }

    // epilogue: bias + store to scratch
    const int n_base = tn * BN + warp_n * 32;
    float2 bias[4];
    #pragma unroll
    for (int nt = 0; nt < 4; ++nt) {
        const int n0 = n_base + nt * 8 + tg * 2;
        bias[nt].x = (n0 < NQ) ? q_b[n0] : 0.0f;
        bias[nt].y = (n0 + 1 < NQ) ? q_b[n0 + 1] : 0.0f;
    }
    #pragma unroll
    for (int mt = 0; mt < 4; ++mt) {
        const int r0 = tm * BM + warp_m * 64 + mt * 16 + g;
        float* p0 = g_proj + (size_t)r0 * NT + n_base;
        float* p1 = p0 + (size_t)8 * NT;
        #pragma unroll
        for (int nt = 0; nt < 4; ++nt) {
            const int no = nt * 8 + tg * 2;
            *reinterpret_cast<float2*>(p0 + no) =
                make_float2(acc[mt][nt][0] + bias[nt].x, acc[mt][nt][1] + bias[nt].y);
            *reinterpret_cast<float2*>(p1 + no) =
                make_float2(acc[mt][nt][2] + bias[nt].x, acc[mt][nt][3] + bias[nt].y);
        }
    }
}

// ---------------------------------------------------------------- score
__global__ void __launch_bounds__(256) score_kernel(
    const float* __restrict__ q_norm_w,
    const float* __restrict__ k_norm_w,
    const float* __restrict__ k_base,
    const float* __restrict__ b,
    float* __restrict__ out)
{
    using namespace cfg;
    const int warp = blockIdx.x * (blockDim.x >> 5) + (threadIdx.x >> 5);
    const int lane = threadIdx.x & 31;
    const int h = warp & (H - 1);
    const int s = warp >> 3;
    const float* base = g_proj + (size_t)s * NT;

    const float4 wq = *reinterpret_cast<const float4*>(q_norm_w + lane * 4);
    const float4 wk = *reinterpret_cast<const float4*>(k_norm_w + lane * 4);
    const float4 kb = *reinterpret_cast<const float4*>(k_base + h * HD + lane * 4);
    const float4 kv = *reinterpret_cast<const float4*>(base + NQ + h * HD + lane * 4);

    float ssk = kv.x * kv.x + kv.y * kv.y + kv.z * kv.z + kv.w * kv.w;
    #pragma unroll
    for (int o = 16; o > 0; o >>= 1) ssk += __shfl_xor_sync(0xFFFFFFFFu, ssk, o);
    const float rk = rsqrtf(ssk * (1.0f / HD) + 1e-6f);
    const float kn0 = kv.x * rk * wk.x;
    const float kn1 = kv.y * rk * wk.y;
    const float kn2 = kv.z * rk * wk.z;
    const float kn3 = kv.w * rk * wk.w;

    const float inv_scale = 0.08838834764831845f;  // 1/sqrt(128)
    float score = 0.0f;
    #pragma unroll
    for (int gi = 0; gi < G; ++gi) {
        const float4 qv = *reinterpret_cast<const float4*>(
            base + h * (G * HD) + gi * HD + lane * 4);
        float s1 = qv.x * qv.x + qv.y * qv.y + qv.z * qv.z + qv.w * qv.w;
        const float qw0 = qv.x * wq.x, qw1 = qv.y * wq.y;
        const float qw2 = qv.z * wq.z, qw3 = qv.w * wq.w;
        float s2 = kn0 * qw0 + kn1 * qw1 + kn2 * qw2 + kn3 * qw3;
        float s3 = kb.x * qw0 + kb.y * qw1 + kb.z * qw2 + kb.w * qw3;
        #pragma unroll
        for (int o = 16; o > 0; o >>= 1) {
            s1 += __shfl_xor_sync(0xFFFFFFFFu, s1, o);
            s2 += __shfl_xor_sync(0xFFFFFFFFu, s2, o);
            s3 += __shfl_xor_sync(0xFFFFFFFFu, s3, o);
        }
        const float rq = rsqrtf(s1 * (1.0f / HD) + 1e-6f);
        const float diff = (s3 - s2) * rq * inv_scale - b[h * G + gi];
        score += 1.0f / (1.0f + expf(diff));
    }
    if (lane == 0) out[h * S + s] = score * 0.25f;
}

// ---------------------------------------------------------------- host
extern "C" void kernel_launch(void* const* d_in, const int* in_sizes, int n_in,
                              void* d_out, int out_size) {
    using namespace cfg;
    const float* hs    = (const float*)d_in[0];
    const float* qw    = (const float*)d_in[1];
    const float* qb    = (const float*)d_in[2];
    const float* kw    = (const float*)d_in[3];
    const float* qnw   = (const float*)d_in[4];
    const float* knw   = (const float*)d_in[5];
    const float* kbase = (const float*)d_in[6];
    const float* bvec  = (const float*)d_in[7];
    float* out         = (float*)d_out;

    static bool attr_set = false;
    if (!attr_set) {
        cudaFuncSetAttribute(proj_gemm_kernel,
                             cudaFuncAttributeMaxDynamicSharedMemorySize, SMEM_BYTES);
        attr_set = true;
    }

    const int conv_blocks = (int)(((size_t)S * D + (size_t)NT * D) / 4 / 256);
    convert_kernel<<<conv_blocks, 256>>>(hs, qw, kw);
    proj_gemm_kernel<<<TM_TILES * TN_TILES, 256, SMEM_BYTES>>>(qb);
    score_kernel<<<(S * H) / 8, 256>>>(qnw, knw, kbase, bvec, out);
}